// round 14
// baseline (speedup 1.0000x reference)
#include <cuda_runtime.h>
#include <cuda_fp16.h>
#include <cstdint>
#include <math.h>

#define BB 1024
#define SS 64
#define EE 100
#define HH 512
#define VV 50000

// ---------------------------------------------------------------------------
// Static device scratch (no allocations allowed)
// g_h:   fp32 hidden, NATURAL order (blend path + tail kernels)
// g_hhf: fp16 hidden, K-PERMUTED within 16-groups (GEMM A path)
// ---------------------------------------------------------------------------
__device__ float    g_h[2][3 * BB * HH];
__device__ __half   g_hhf[2][3 * BB * HH];
__device__ float    g_eqc[BB * HH];
__device__ __half   g_wpk[(size_t)3 * 16 * 128 * 640];  // packed W, 7.9 MB
__device__ __half   g_embp[(size_t)3 * VV * 128];       // packed emb, 38.4 MB

struct Enc {
    const int*   tok;
    const float* emb;
    const float* wih;
    const float* whh;
    const float* bih;
    const float* bhh;
};
struct EncPack { Enc e[3]; };

__device__ __forceinline__ float sigmoidf_(float x) {
    return 1.0f / (1.0f + __expf(-x));
}

// ===========================================================================
// PTX helpers (sm_80-portable)
// ===========================================================================
__device__ __forceinline__ void cp16(uint32_t dst, const void* src) {
    asm volatile("cp.async.cg.shared.global [%0], [%1], 16;" :: "r"(dst), "l"(src));
}
#define CP_COMMIT() asm volatile("cp.async.commit_group;" ::: "memory")
#define CP_WAITG1() asm volatile("cp.async.wait_group 1;" ::: "memory")

__device__ __forceinline__ uint32_t smem_u32(const void* p) {
    uint32_t a;
    asm("{ .reg .u64 t; cvta.to.shared.u64 t, %1; cvt.u32.u64 %0, t; }" : "=r"(a) : "l"(p));
    return a;
}
__device__ __forceinline__ void mma16(float* d, const uint32_t* a, uint32_t b0, uint32_t b1) {
    asm volatile("mma.sync.aligned.m16n8k16.row.col.f32.f16.f16.f32 "
                 "{%0,%1,%2,%3}, {%4,%5,%6,%7}, {%8,%9}, {%0,%1,%2,%3};"
                 : "+f"(d[0]), "+f"(d[1]), "+f"(d[2]), "+f"(d[3])
                 : "r"(a[0]), "r"(a[1]), "r"(a[2]), "r"(a[3]), "r"(b0), "r"(b1));
}

// K-permutation within 16-groups for m16n8k16 frags:
// source k -> position 4*((k>>1)&3) + (k&1) + 2*((k>>3)&1)
// => thread tg's halves {2tg, 2tg+1, 2tg+8, 2tg+9} land at positions 4tg..4tg+3.
__device__ __forceinline__ int p16(int k) {
    return (((k >> 1) & 3) << 2) | (k & 1) | (((k >> 3) & 1) << 1);
}

// ===========================================================================
// Init + pack kernels
// ===========================================================================
__global__ void zero_h_kernel() {
    size_t i = (size_t)blockIdx.x * blockDim.x + threadIdx.x;
    if (i < (size_t)3 * BB * HH) {
        g_h[0][i]   = 0.0f;
        g_hhf[0][i] = __float2half_rn(0.0f);
    }
}

// W panels: [e][jt(16)][n(128)][k(640), p16-permuted].  n-tile nt=n>>3: jg=nt>>2,
// sec=nt&3, j=jt*32+jg*8+(n&7).  k<512: h-part (sec0..2=whh_r/z/n, sec3=0);
// k>=512: kx=k-512 (sec0/1=wih_r/z, sec2=0, sec3=wih_n; kx>=100 -> 0).
__global__ void pack_w_kernel(EncPack P) {
    size_t id = (size_t)blockIdx.x * blockDim.x + threadIdx.x;
    if (id >= (size_t)3 * 16 * 128 * 640) return;
    int k  = (int)(id % 640);
    int n  = (int)((id / 640) % 128);
    int jt = (int)((id / (640 * 128)) % 16);
    int e  = (int)(id / (640 * 128 * 16));
    int nt = n >> 3, jg = nt >> 2, sec = nt & 3, jj = n & 7;
    int j = jt * 32 + jg * 8 + jj;
    float v = 0.0f;
    if (k < 512) {
        if (sec < 3) v = P.e[e].whh[(size_t)(sec * HH + j) * HH + k];
    } else {
        int kx = k - 512;
        if (kx < EE) {
            if (sec < 2)       v = P.e[e].wih[(size_t)(sec * HH + j) * EE + kx];
            else if (sec == 3) v = P.e[e].wih[(size_t)(2 * HH + j) * EE + kx];
        }
    }
    size_t dst = (((size_t)(e * 16 + jt) * 128 + n) * 640) + (k & ~15) + p16(k & 15);
    g_wpk[dst] = __float2half_rn(v);
}

// emb: [e][v][k(128), p16-permuted, zero-padded past E=100]
__global__ void pack_emb_kernel(EncPack P) {
    size_t id = (size_t)blockIdx.x * blockDim.x + threadIdx.x;
    if (id >= (size_t)3 * VV * 128) return;
    int k = (int)(id & 127);
    int v = (int)((id >> 7) % VV);
    int e = (int)(id / ((size_t)VV * 128));
    float x = (k < EE) ? P.e[e].emb[(size_t)v * EE + k] : 0.0f;
    g_embp[((size_t)e * VV + v) * 128 + (k & ~15) + p16(k & 15)] = __float2half_rn(x);
}

// ===========================================================================
// Fused GRU step, fp16 m16n8k16 (fp32 accum).  M=128 x N=128 x K=640
// (10 chunks of 64).  N sections per 8-j group: [r | z | h_n | i_n].
// ZERO-SECTION SKIP: h-chunks (c<8) compute sections {r,z,h_n} only
// (sec3 B-block is structurally zero); x-chunks (c>=8) compute {r,z,i_n}
// (sec2 zero).  Chunk 9 group g=3 (kx 112..127 >= E) skipped entirely.
// B loader skips the dead section's rows.  27% fewer HMMA, 25% fewer B loads.
// 3-stage cp.async pipeline, one __syncthreads per chunk.
// XOR swizzle: uint4 slot q -> q ^ ((row&3)<<1); reader uses same term.
// grid (16, 8, 3), block 256 (warps 4m x 2n), 2 CTAs/SM, 98.8 KB dyn smem.
// ===========================================================================
#define NCHK 10
#define STGW (128 * 32)          // uint32 words per stage per operand

__global__ __launch_bounds__(256, 2) void step_tc_kernel(EncPack P, int t, int p) {
    extern __shared__ uint32_t dsm[];
    uint32_t* As = dsm;                       // [3][STGW]
    uint32_t* Bs = dsm + 3 * STGW;            // [3][STGW]
    int*      stok = (int*)(dsm + 6 * STGW);  // [128]

    const int e  = blockIdx.z;
    const Enc ep = P.e[e];
    const int jt = blockIdx.x;
    const int j0 = jt * 32;
    const int b0 = blockIdx.y * 128;

    const float* __restrict__ hin  = g_h[p]     + (size_t)e * BB * HH;
    float*       __restrict__ hout = g_h[p ^ 1] + (size_t)e * BB * HH;
    const __half* __restrict__ hhf  = g_hhf[p]     + (size_t)e * BB * HH;
    __half*       __restrict__ hhfo = g_hhf[p ^ 1] + (size_t)e * BB * HH;
    const __half* __restrict__ Wp   = g_wpk  + ((size_t)(e * 16 + jt) * 128) * 640;
    const __half* __restrict__ embp = g_embp + (size_t)e * VV * 128;

    const int tid = threadIdx.x;
    const int lane = tid & 31, wid = tid >> 5;
    const int gr = lane >> 2, tg = lane & 3;
    const int warp_m = wid & 3, warp_n = wid >> 2;
    const int xg = gr & 3;                    // row&3 of every row this thread reads

    const uint32_t sA = smem_u32(As), sB = smem_u32(Bs);

    if (tid < 128) stok[tid] = ep.tok[(b0 + tid) * SS + t];
    __syncthreads();

    // Per-thread swizzled word offsets for the 4 k16-iterations of a chunk.
    // Unswizzled word w = 8g + 2tg; slot = (w>>2) ^ (xg<<1); woff = slot*4+(w&3).
    int woff[4];
#pragma unroll
    for (int g = 0; g < 4; g++) {
        int w = 8 * g + 2 * tg;
        woff[g] = (((w >> 2) ^ (xg << 1)) << 2) | (w & 3);
    }

    float acc[2][2][4][4];           // [mt][jg_l][sec][dreg]
#pragma unroll
    for (int a = 0; a < 2; a++)
#pragma unroll
        for (int b = 0; b < 2; b++)
#pragma unroll
            for (int s = 0; s < 4; s++)
#pragma unroll
                for (int c = 0; c < 4; c++) acc[a][b][s][c] = 0.0f;

    auto load_chunk = [&](int c, int st) {
        const uint32_t aB = sA + (uint32_t)st * STGW * 4;
        const uint32_t bB = sB + (uint32_t)st * STGW * 4;
        const int skip_sec = (c < 8) ? 3 : 2;    // dead B section this chunk
#pragma unroll
        for (int it = 0; it < 4; it++) {
            int idx = tid + it * 256;            // [0,1024): row 0..127, kq 0..7
            int row = idx >> 3, kq = idx & 7;
            int q = kq ^ ((row & 3) << 1);       // swizzled uint4 slot
            uint32_t dof = (uint32_t)(row * 32 + q * 4) * 4;
            const void* asrc = (c < 8)
                ? (const void*)(hhf + (size_t)(b0 + row) * HH + c * 64 + kq * 8)
                : (const void*)(embp + (size_t)stok[row] * 128 + (c - 8) * 64 + kq * 8);
            cp16(aB + dof, asrc);
            if (((row >> 3) & 3) != skip_sec)
                cp16(bB + dof, Wp + (size_t)row * 640 + c * 64 + kq * 8);
        }
    };

    load_chunk(0, 0); CP_COMMIT();
    load_chunk(1, 1); CP_COMMIT();

    int s_cur = 0;                    // stage of chunk c
    int s_ld  = 2;                    // stage of chunk c+2
    for (int c = 0; c < NCHK; c++) {
        CP_WAITG1();                  // stage s_cur ready; next chunk may be in flight
        __syncthreads();              // all warps done with stage s_ld's old contents
        if (c + 2 < NCHK) {
            load_chunk(c + 2, s_ld);
            CP_COMMIT();
        }
        const uint32_t* Ast = As + s_cur * STGW;
        const uint32_t* Bst = Bs + s_cur * STGW;
        const int alt_sec = (c < 8) ? 2 : 3;     // third LIVE section this chunk
        const int ng = (c == 9) ? 3 : 4;         // chunk 9: kx 112..127 all zero
#pragma unroll
        for (int g = 0; g < 4; g++) {
            if (g >= ng) break;
            const int uw = woff[g];
            uint32_t a[2][4];
#pragma unroll
            for (int mt = 0; mt < 2; mt++) {
                int rb = warp_m * 32 + mt * 16 + gr;
                uint2 lo = *(const uint2*)&Ast[rb * 32 + uw];
                uint2 hi = *(const uint2*)&Ast[(rb + 8) * 32 + uw];
                a[mt][0] = lo.x; a[mt][2] = lo.y; a[mt][1] = hi.x; a[mt][3] = hi.y;
            }
#pragma unroll
            for (int jg_l = 0; jg_l < 2; jg_l++) {
#pragma unroll
                for (int ss = 0; ss < 3; ss++) {
                    int sec = (ss < 2) ? ss : alt_sec;
                    int n = warp_n * 64 + (jg_l * 4 + sec) * 8 + gr;
                    uint2 bb = *(const uint2*)&Bst[n * 32 + uw];
                    mma16(acc[0][jg_l][sec], a[0], bb.x, bb.y);
                    mma16(acc[1][jg_l][sec], a[1], bb.x, bb.y);
                }
            }
        }
        s_cur = (s_cur == 2) ? 0 : s_cur + 1;
        s_ld  = (s_ld  == 2) ? 0 : s_ld  + 1;
    }

    // ---- GRU epilogue (per-thread, in-register) ----
    float br[2][2], bz[2][2], bnh[2][2], bni[2][2];
    int   jp[2][2];
#pragma unroll
    for (int jg_l = 0; jg_l < 2; jg_l++)
#pragma unroll
        for (int cc = 0; cc < 2; cc++) {
            int j = j0 + (warp_n * 2 + jg_l) * 8 + tg * 2 + cc;
            br[jg_l][cc]  = ep.bih[j]          + ep.bhh[j];
            bz[jg_l][cc]  = ep.bih[HH + j]     + ep.bhh[HH + j];
            bnh[jg_l][cc] = ep.bhh[2 * HH + j];
            bni[jg_l][cc] = ep.bih[2 * HH + j];
            jp[jg_l][cc]  = (j & ~15) | p16(j & 15);   // fp16 permuted pos
        }

#pragma unroll
    for (int mt = 0; mt < 2; mt++) {
#pragma unroll
        for (int rp = 0; rp < 2; rp++) {
            const int row = b0 + warp_m * 32 + mt * 16 + gr + rp * 8;
            const float* hrow = hin + (size_t)row * HH;
            float*       orow = hout + (size_t)row * HH;
            __half*      ohrow = hhfo + (size_t)row * HH;
#pragma unroll
            for (int jg_l = 0; jg_l < 2; jg_l++) {
#pragma unroll
                for (int cc = 0; cc < 2; cc++) {
                    const int j = j0 + (warp_n * 2 + jg_l) * 8 + tg * 2 + cc;
                    const int k = rp * 2 + cc;
                    float r = sigmoidf_(acc[mt][jg_l][0][k] + br[jg_l][cc]);
                    float z = sigmoidf_(acc[mt][jg_l][1][k] + bz[jg_l][cc]);
                    float n = tanhf(acc[mt][jg_l][3][k] + bni[jg_l][cc] +
                                    r * (acc[mt][jg_l][2][k] + bnh[jg_l][cc]));
                    float hv = (1.0f - z) * n + z * hrow[j];
                    orow[j] = hv;                              // fp32 master
                    ohrow[jp[jg_l][cc]] = __float2half_rn(hv); // fp16 GEMM copy
                }
            }
        }
    }
}

// ===========================================================================
// eqc = ((eq + ec) * 0.5) @ lin_w^T + lin_b   (natural-order fp32 h)
// ===========================================================================
__global__ __launch_bounds__(128) void eqc_kernel(const float* __restrict__ lin_w,
                                                  const float* __restrict__ lin_b,
                                                  int p) {
    const float* __restrict__ hq = g_h[p];
    const float* __restrict__ hc = g_h[p] + (size_t)BB * HH;
    const int n0 = blockIdx.x * 64;
    const int b0 = blockIdx.y * 64;

    __shared__ float As[16][65];
    __shared__ float Bs[16][65];

    const int tid = threadIdx.x;
    const int tx = tid & 15, ty = tid >> 4;

    float acc[8][4];
#pragma unroll
    for (int i = 0; i < 8; i++)
#pragma unroll
        for (int j = 0; j < 4; j++) acc[i][j] = 0.0f;

    for (int k0 = 0; k0 < HH; k0 += 16) {
#pragma unroll
        for (int l = 0; l < 8; l++) {
            int idx = tid + l * 128;
            int k = idx & 15, i = idx >> 4;
            size_t ga = (size_t)(b0 + i) * HH + (k0 + k);
            As[k][i] = 0.5f * (hq[ga] + hc[ga]);
            Bs[k][i] = lin_w[(size_t)(n0 + i) * HH + (k0 + k)];
        }
        __syncthreads();
#pragma unroll
        for (int k = 0; k < 16; k++) {
            float a[8], b[4];
#pragma unroll
            for (int i = 0; i < 8; i++) a[i] = As[k][ty * 8 + i];
#pragma unroll
            for (int j = 0; j < 4; j++) b[j] = Bs[k][tx * 4 + j];
#pragma unroll
            for (int i = 0; i < 8; i++)
#pragma unroll
                for (int j = 0; j < 4; j++) acc[i][j] += a[i] * b[j];
        }
        __syncthreads();
    }

    float bi[4];
#pragma unroll
    for (int j = 0; j < 4; j++) bi[j] = lin_b[n0 + tx * 4 + j];
#pragma unroll
    for (int i = 0; i < 8; i++) {
        size_t base = (size_t)(b0 + ty * 8 + i) * HH + n0 + tx * 4;
#pragma unroll
        for (int j = 0; j < 4; j++) g_eqc[base + j] = acc[i][j] + bi[j];
    }
}

// ===========================================================================
// logits[m] = X_m @ er^T, writes d_out
// ===========================================================================
__global__ __launch_bounds__(128) void logits_kernel(float* __restrict__ out, int p) {
    const int m = blockIdx.z;
    const float* __restrict__ X  = (m == 0) ? g_h[p]
                                 : (m == 1) ? g_h[p] + (size_t)BB * HH
                                            : g_eqc;
    const float* __restrict__ er = g_h[p] + (size_t)2 * BB * HH;
    const int n0 = blockIdx.x * 64;
    const int b0 = blockIdx.y * 64;

    __shared__ float As[16][65];
    __shared__ float Bs[16][65];

    const int tid = threadIdx.x;
    const int tx = tid & 15, ty = tid >> 4;

    float acc[8][4];
#pragma unroll
    for (int i = 0; i < 8; i++)
#pragma unroll
        for (int j = 0; j < 4; j++) acc[i][j] = 0.0f;

    for (int k0 = 0; k0 < HH; k0 += 16) {
#pragma unroll
        for (int l = 0; l < 8; l++) {
            int idx = tid + l * 128;
            int k = idx & 15, i = idx >> 4;
            As[k][i] = X[(size_t)(b0 + i) * HH + (k0 + k)];
            Bs[k][i] = er[(size_t)(n0 + i) * HH + (k0 + k)];
        }
        __syncthreads();
#pragma unroll
        for (int k = 0; k < 16; k++) {
            float a[8], b[4];
#pragma unroll
            for (int i = 0; i < 8; i++) a[i] = As[k][ty * 8 + i];
#pragma unroll
            for (int j = 0; j < 4; j++) b[j] = Bs[k][tx * 4 + j];
#pragma unroll
            for (int i = 0; i < 8; i++)
#pragma unroll
                for (int j = 0; j < 4; j++) acc[i][j] += a[i] * b[j];
        }
        __syncthreads();
    }

#pragma unroll
    for (int i = 0; i < 8; i++) {
        size_t base = (size_t)m * BB * BB + (size_t)(b0 + ty * 8 + i) * BB + n0 + tx * 4;
#pragma unroll
        for (int j = 0; j < 4; j++) out[base + j] = acc[i][j];
    }
}

// ===========================================================================
// Row softmax over 3*B rows of length B, in-place on d_out.
// ===========================================================================
__global__ __launch_bounds__(256) void softmax_kernel(float* __restrict__ out) {
    float* prow = out + (size_t)blockIdx.x * BB;
    __shared__ float red[256];
    const int tid = threadIdx.x;

    float v[4];
    float mx = -1e30f;
#pragma unroll
    for (int l = 0; l < 4; l++) {
        v[l] = prow[tid + l * 256];
        mx = fmaxf(mx, v[l]);
    }
    red[tid] = mx;
    __syncthreads();
    for (int s = 128; s > 0; s >>= 1) {
        if (tid < s) red[tid] = fmaxf(red[tid], red[tid + s]);
        __syncthreads();
    }
    mx = red[0];
    __syncthreads();

    float sum = 0.0f;
#pragma unroll
    for (int l = 0; l < 4; l++) {
        v[l] = __expf(v[l] - mx);
        sum += v[l];
    }
    red[tid] = sum;
    __syncthreads();
    for (int s = 128; s > 0; s >>= 1) {
        if (tid < s) red[tid] += red[tid + s];
        __syncthreads();
    }
    float inv = 1.0f / red[0];
#pragma unroll
    for (int l = 0; l < 4; l++) prow[tid + l * 256] = v[l] * inv;
}

// ===========================================================================
// Launch
// ===========================================================================
extern "C" void kernel_launch(void* const* d_in, const int* in_sizes, int n_in,
                              void* d_out, int out_size) {
    (void)in_sizes; (void)n_in; (void)out_size;

    EncPack P;
    const int* toks[3] = { (const int*)d_in[0], (const int*)d_in[1], (const int*)d_in[2] };
    for (int e = 0; e < 3; e++) {
        int b = 3 + e * 5;
        P.e[e].tok = toks[e];
        P.e[e].emb = (const float*)d_in[b + 0];
        P.e[e].wih = (const float*)d_in[b + 1];
        P.e[e].whh = (const float*)d_in[b + 2];
        P.e[e].bih = (const float*)d_in[b + 3];
        P.e[e].bhh = (const float*)d_in[b + 4];
    }
    const float* lin_w = (const float*)d_in[18];
    const float* lin_b = (const float*)d_in[19];
    float* out = (float*)d_out;

    const int SMEM_DYN = (6 * STGW) * 4 + 128 * 4;   // 98816 B
    cudaFuncSetAttribute(step_tc_kernel,
                         cudaFuncAttributeMaxDynamicSharedMemorySize, SMEM_DYN);

    zero_h_kernel<<<(3 * BB * HH + 255) / 256, 256>>>();
    {
        size_t n = (size_t)3 * 16 * 128 * 640;
        pack_w_kernel<<<(unsigned)((n + 255) / 256), 256>>>(P);
    }
    {
        size_t n = (size_t)3 * VV * 128;
        pack_emb_kernel<<<(unsigned)((n + 255) / 256), 256>>>(P);
    }

    int p = 0;
    for (int t = SS - 1; t >= 0; --t) {
        step_tc_kernel<<<dim3(16, BB / 128, 3), 256, SMEM_DYN>>>(P, t, p);
        p ^= 1;
    }

    eqc_kernel<<<dim3(HH / 64, BB / 64), 128>>>(lin_w, lin_b, p);
    logits_kernel<<<dim3(BB / 64, BB / 64, 3), 128>>>(out, p);
    softmax_kernel<<<3 * BB, 256>>>(out);
}

// round 16
// speedup vs baseline: 2.0642x; 2.0642x over previous
#include <cuda_runtime.h>
#include <cuda_fp16.h>
#include <cstdint>
#include <math.h>

#define BB 1024
#define SS 64
#define EE 100
#define HH 512
#define VV 50000

// ---------------------------------------------------------------------------
// Static device scratch (no allocations allowed)
// g_h:   fp32 hidden, NATURAL order (blend path + tail kernels)
// g_hhf: fp16 hidden, K-PERMUTED within 16-groups (GEMM A path)
// ---------------------------------------------------------------------------
__device__ float    g_h[2][3 * BB * HH];
__device__ __half   g_hhf[2][3 * BB * HH];
__device__ float    g_eqc[BB * HH];
__device__ __half   g_wpk[(size_t)3 * 16 * 128 * 640];  // packed W, 7.9 MB
__device__ __half   g_embp[(size_t)3 * VV * 128];       // packed emb, 38.4 MB

struct Enc {
    const int*   tok;
    const float* emb;
    const float* wih;
    const float* whh;
    const float* bih;
    const float* bhh;
};
struct EncPack { Enc e[3]; };

__device__ __forceinline__ float sigmoidf_(float x) {
    return 1.0f / (1.0f + __expf(-x));
}

// ===========================================================================
// PTX helpers (sm_80-portable)
// ===========================================================================
__device__ __forceinline__ void cp16(uint32_t dst, const void* src) {
    asm volatile("cp.async.cg.shared.global [%0], [%1], 16;" :: "r"(dst), "l"(src));
}
#define CP_COMMIT() asm volatile("cp.async.commit_group;" ::: "memory")
#define CP_WAITG1() asm volatile("cp.async.wait_group 1;" ::: "memory")

__device__ __forceinline__ uint32_t smem_u32(const void* p) {
    uint32_t a;
    asm("{ .reg .u64 t; cvta.to.shared.u64 t, %1; cvt.u32.u64 %0, t; }" : "=r"(a) : "l"(p));
    return a;
}
__device__ __forceinline__ void mma16(float* d, const uint32_t* a, uint32_t b0, uint32_t b1) {
    asm volatile("mma.sync.aligned.m16n8k16.row.col.f32.f16.f16.f32 "
                 "{%0,%1,%2,%3}, {%4,%5,%6,%7}, {%8,%9}, {%0,%1,%2,%3};"
                 : "+f"(d[0]), "+f"(d[1]), "+f"(d[2]), "+f"(d[3])
                 : "r"(a[0]), "r"(a[1]), "r"(a[2]), "r"(a[3]), "r"(b0), "r"(b1));
}

// K-permutation within 16-groups for m16n8k16 frags:
// source k -> position 4*((k>>1)&3) + (k&1) + 2*((k>>3)&1)
// => thread tg's halves {2tg, 2tg+1, 2tg+8, 2tg+9} land at positions 4tg..4tg+3.
__device__ __forceinline__ int p16(int k) {
    return (((k >> 1) & 3) << 2) | (k & 1) | (((k >> 3) & 1) << 1);
}

// ===========================================================================
// Chunk compute: sections {0, 1, ALT} over NG k16-groups.
// ALL indices compile-time -> acc/a arrays stay in registers (the round-14
// runtime-index variant demoted acc to local memory; never again).
// ===========================================================================
template<int ALT, int NG>
__device__ __forceinline__ void compute_chunk(
    float (&acc)[2][2][4][4],
    const uint32_t* __restrict__ Ast, const uint32_t* __restrict__ Bst,
    int warp_m, int warp_n, int gr, int tg, int xg)
{
#pragma unroll
    for (int g = 0; g < NG; g++) {
        const int w  = 8 * g + 2 * tg;
        const int uw = (((w >> 2) ^ (xg << 1)) << 2) | (w & 3);
        uint32_t a[2][4];
#pragma unroll
        for (int mt = 0; mt < 2; mt++) {
            int rb = warp_m * 32 + mt * 16 + gr;
            uint2 lo = *(const uint2*)&Ast[rb * 32 + uw];
            uint2 hi = *(const uint2*)&Ast[(rb + 8) * 32 + uw];
            a[mt][0] = lo.x; a[mt][2] = lo.y; a[mt][1] = hi.x; a[mt][3] = hi.y;
        }
#pragma unroll
        for (int jg_l = 0; jg_l < 2; jg_l++) {
            {
                int n = warp_n * 64 + (jg_l * 4 + 0) * 8 + gr;
                uint2 bb = *(const uint2*)&Bst[n * 32 + uw];
                mma16(acc[0][jg_l][0], a[0], bb.x, bb.y);
                mma16(acc[1][jg_l][0], a[1], bb.x, bb.y);
            }
            {
                int n = warp_n * 64 + (jg_l * 4 + 1) * 8 + gr;
                uint2 bb = *(const uint2*)&Bst[n * 32 + uw];
                mma16(acc[0][jg_l][1], a[0], bb.x, bb.y);
                mma16(acc[1][jg_l][1], a[1], bb.x, bb.y);
            }
            {
                int n = warp_n * 64 + (jg_l * 4 + ALT) * 8 + gr;
                uint2 bb = *(const uint2*)&Bst[n * 32 + uw];
                mma16(acc[0][jg_l][ALT], a[0], bb.x, bb.y);
                mma16(acc[1][jg_l][ALT], a[1], bb.x, bb.y);
            }
        }
    }
}

// ===========================================================================
// Init + pack kernels
// ===========================================================================
__global__ void zero_h_kernel() {
    size_t i = (size_t)blockIdx.x * blockDim.x + threadIdx.x;
    if (i < (size_t)3 * BB * HH) {
        g_h[0][i]   = 0.0f;
        g_hhf[0][i] = __float2half_rn(0.0f);
    }
}

// W panels: [e][jt(16)][n(128)][k(640), p16-permuted].  n-tile nt=n>>3: jg=nt>>2,
// sec=nt&3, j=jt*32+jg*8+(n&7).  k<512: h-part (sec0..2=whh_r/z/n, sec3=0);
// k>=512: kx=k-512 (sec0/1=wih_r/z, sec2=0, sec3=wih_n; kx>=100 -> 0).
__global__ void pack_w_kernel(EncPack P) {
    size_t id = (size_t)blockIdx.x * blockDim.x + threadIdx.x;
    if (id >= (size_t)3 * 16 * 128 * 640) return;
    int k  = (int)(id % 640);
    int n  = (int)((id / 640) % 128);
    int jt = (int)((id / (640 * 128)) % 16);
    int e  = (int)(id / (640 * 128 * 16));
    int nt = n >> 3, jg = nt >> 2, sec = nt & 3, jj = n & 7;
    int j = jt * 32 + jg * 8 + jj;
    float v = 0.0f;
    if (k < 512) {
        if (sec < 3) v = P.e[e].whh[(size_t)(sec * HH + j) * HH + k];
    } else {
        int kx = k - 512;
        if (kx < EE) {
            if (sec < 2)       v = P.e[e].wih[(size_t)(sec * HH + j) * EE + kx];
            else if (sec == 3) v = P.e[e].wih[(size_t)(2 * HH + j) * EE + kx];
        }
    }
    size_t dst = (((size_t)(e * 16 + jt) * 128 + n) * 640) + (k & ~15) + p16(k & 15);
    g_wpk[dst] = __float2half_rn(v);
}

// emb: [e][v][k(128), p16-permuted, zero-padded past E=100]
__global__ void pack_emb_kernel(EncPack P) {
    size_t id = (size_t)blockIdx.x * blockDim.x + threadIdx.x;
    if (id >= (size_t)3 * VV * 128) return;
    int k = (int)(id & 127);
    int v = (int)((id >> 7) % VV);
    int e = (int)(id / ((size_t)VV * 128));
    float x = (k < EE) ? P.e[e].emb[(size_t)v * EE + k] : 0.0f;
    g_embp[((size_t)e * VV + v) * 128 + (k & ~15) + p16(k & 15)] = __float2half_rn(x);
}

// ===========================================================================
// Fused GRU step, fp16 m16n8k16 (fp32 accum).  M=128 x N=128 x K=640
// (10 chunks of 64).  N sections per 8-j group: [r | z | h_n | i_n].
// ZERO-SECTION SKIP (compile-time): h-chunks (c<8) -> compute_chunk<2,4>
// (sec3 dead); chunk 8 -> <3,4> (sec2 dead); chunk 9 -> <3,3> (sec2 dead,
// g=3 all-zero past E).  27% fewer HMMA, 25% fewer B loads.
// 3-stage cp.async pipeline, one __syncthreads per chunk.
// XOR swizzle: uint4 slot q -> q ^ ((row&3)<<1); reader uses same term.
// grid (16, 8, 3), block 256 (warps 4m x 2n), 2 CTAs/SM, 98.8 KB dyn smem.
// ===========================================================================
#define NCHK 10
#define STGW (128 * 32)          // uint32 words per stage per operand

__global__ __launch_bounds__(256, 2) void step_tc_kernel(EncPack P, int t, int p) {
    extern __shared__ uint32_t dsm[];
    uint32_t* As = dsm;                       // [3][STGW]
    uint32_t* Bs = dsm + 3 * STGW;            // [3][STGW]
    int*      stok = (int*)(dsm + 6 * STGW);  // [128]

    const int e  = blockIdx.z;
    const Enc ep = P.e[e];
    const int jt = blockIdx.x;
    const int j0 = jt * 32;
    const int b0 = blockIdx.y * 128;

    const float* __restrict__ hin  = g_h[p]     + (size_t)e * BB * HH;
    float*       __restrict__ hout = g_h[p ^ 1] + (size_t)e * BB * HH;
    const __half* __restrict__ hhf  = g_hhf[p]     + (size_t)e * BB * HH;
    __half*       __restrict__ hhfo = g_hhf[p ^ 1] + (size_t)e * BB * HH;
    const __half* __restrict__ Wp   = g_wpk  + ((size_t)(e * 16 + jt) * 128) * 640;
    const __half* __restrict__ embp = g_embp + (size_t)e * VV * 128;

    const int tid = threadIdx.x;
    const int lane = tid & 31, wid = tid >> 5;
    const int gr = lane >> 2, tg = lane & 3;
    const int warp_m = wid & 3, warp_n = wid >> 2;
    const int xg = gr & 3;                    // row&3 of every row this thread reads

    const uint32_t sA = smem_u32(As), sB = smem_u32(Bs);

    if (tid < 128) stok[tid] = ep.tok[(b0 + tid) * SS + t];
    __syncthreads();

    float acc[2][2][4][4];           // [mt][jg_l][sec][dreg]
#pragma unroll
    for (int a = 0; a < 2; a++)
#pragma unroll
        for (int b = 0; b < 2; b++)
#pragma unroll
            for (int s = 0; s < 4; s++)
#pragma unroll
                for (int c = 0; c < 4; c++) acc[a][b][s][c] = 0.0f;

    auto load_chunk = [&](int c, int st) {
        const uint32_t aB = sA + (uint32_t)st * STGW * 4;
        const uint32_t bB = sB + (uint32_t)st * STGW * 4;
        const int skip_sec = (c < 8) ? 3 : 2;    // dead B section this chunk
#pragma unroll
        for (int it = 0; it < 4; it++) {
            int idx = tid + it * 256;            // [0,1024): row 0..127, kq 0..7
            int row = idx >> 3, kq = idx & 7;
            int q = kq ^ ((row & 3) << 1);       // swizzled uint4 slot
            uint32_t dof = (uint32_t)(row * 32 + q * 4) * 4;
            const void* asrc = (c < 8)
                ? (const void*)(hhf + (size_t)(b0 + row) * HH + c * 64 + kq * 8)
                : (const void*)(embp + (size_t)stok[row] * 128 + (c - 8) * 64 + kq * 8);
            cp16(aB + dof, asrc);
            if (((row >> 3) & 3) != skip_sec)
                cp16(bB + dof, Wp + (size_t)row * 640 + c * 64 + kq * 8);
        }
    };

    load_chunk(0, 0); CP_COMMIT();
    load_chunk(1, 1); CP_COMMIT();

    int s_cur = 0;                    // stage of chunk c
    int s_ld  = 2;                    // stage of chunk c+2
    for (int c = 0; c < NCHK; c++) {
        CP_WAITG1();                  // stage s_cur ready; next chunk may be in flight
        __syncthreads();              // all warps done with stage s_ld's old contents
        if (c + 2 < NCHK) {
            load_chunk(c + 2, s_ld);
            CP_COMMIT();
        }
        const uint32_t* Ast = As + s_cur * STGW;
        const uint32_t* Bst = Bs + s_cur * STGW;
        if (c < 8)
            compute_chunk<2, 4>(acc, Ast, Bst, warp_m, warp_n, gr, tg, xg);
        else if (c == 8)
            compute_chunk<3, 4>(acc, Ast, Bst, warp_m, warp_n, gr, tg, xg);
        else
            compute_chunk<3, 3>(acc, Ast, Bst, warp_m, warp_n, gr, tg, xg);
        s_cur = (s_cur == 2) ? 0 : s_cur + 1;
        s_ld  = (s_ld  == 2) ? 0 : s_ld  + 1;
    }

    // ---- GRU epilogue (per-thread, in-register) ----
    float br[2][2], bz[2][2], bnh[2][2], bni[2][2];
    int   jp[2][2];
#pragma unroll
    for (int jg_l = 0; jg_l < 2; jg_l++)
#pragma unroll
        for (int cc = 0; cc < 2; cc++) {
            int j = j0 + (warp_n * 2 + jg_l) * 8 + tg * 2 + cc;
            br[jg_l][cc]  = ep.bih[j]          + ep.bhh[j];
            bz[jg_l][cc]  = ep.bih[HH + j]     + ep.bhh[HH + j];
            bnh[jg_l][cc] = ep.bhh[2 * HH + j];
            bni[jg_l][cc] = ep.bih[2 * HH + j];
            jp[jg_l][cc]  = (j & ~15) | p16(j & 15);   // fp16 permuted pos
        }

#pragma unroll
    for (int mt = 0; mt < 2; mt++) {
#pragma unroll
        for (int rp = 0; rp < 2; rp++) {
            const int row = b0 + warp_m * 32 + mt * 16 + gr + rp * 8;
            const float* hrow = hin + (size_t)row * HH;
            float*       orow = hout + (size_t)row * HH;
            __half*      ohrow = hhfo + (size_t)row * HH;
#pragma unroll
            for (int jg_l = 0; jg_l < 2; jg_l++) {
#pragma unroll
                for (int cc = 0; cc < 2; cc++) {
                    const int j = j0 + (warp_n * 2 + jg_l) * 8 + tg * 2 + cc;
                    const int k = rp * 2 + cc;
                    float r = sigmoidf_(acc[mt][jg_l][0][k] + br[jg_l][cc]);
                    float z = sigmoidf_(acc[mt][jg_l][1][k] + bz[jg_l][cc]);
                    float n = tanhf(acc[mt][jg_l][3][k] + bni[jg_l][cc] +
                                    r * (acc[mt][jg_l][2][k] + bnh[jg_l][cc]));
                    float hv = (1.0f - z) * n + z * hrow[j];
                    orow[j] = hv;                              // fp32 master
                    ohrow[jp[jg_l][cc]] = __float2half_rn(hv); // fp16 GEMM copy
                }
            }
        }
    }
}

// ===========================================================================
// eqc = ((eq + ec) * 0.5) @ lin_w^T + lin_b   (natural-order fp32 h)
// ===========================================================================
__global__ __launch_bounds__(128) void eqc_kernel(const float* __restrict__ lin_w,
                                                  const float* __restrict__ lin_b,
                                                  int p) {
    const float* __restrict__ hq = g_h[p];
    const float* __restrict__ hc = g_h[p] + (size_t)BB * HH;
    const int n0 = blockIdx.x * 64;
    const int b0 = blockIdx.y * 64;

    __shared__ float As[16][65];
    __shared__ float Bs[16][65];

    const int tid = threadIdx.x;
    const int tx = tid & 15, ty = tid >> 4;

    float acc[8][4];
#pragma unroll
    for (int i = 0; i < 8; i++)
#pragma unroll
        for (int j = 0; j < 4; j++) acc[i][j] = 0.0f;

    for (int k0 = 0; k0 < HH; k0 += 16) {
#pragma unroll
        for (int l = 0; l < 8; l++) {
            int idx = tid + l * 128;
            int k = idx & 15, i = idx >> 4;
            size_t ga = (size_t)(b0 + i) * HH + (k0 + k);
            As[k][i] = 0.5f * (hq[ga] + hc[ga]);
            Bs[k][i] = lin_w[(size_t)(n0 + i) * HH + (k0 + k)];
        }
        __syncthreads();
#pragma unroll
        for (int k = 0; k < 16; k++) {
            float a[8], b[4];
#pragma unroll
            for (int i = 0; i < 8; i++) a[i] = As[k][ty * 8 + i];
#pragma unroll
            for (int j = 0; j < 4; j++) b[j] = Bs[k][tx * 4 + j];
#pragma unroll
            for (int i = 0; i < 8; i++)
#pragma unroll
                for (int j = 0; j < 4; j++) acc[i][j] += a[i] * b[j];
        }
        __syncthreads();
    }

    float bi[4];
#pragma unroll
    for (int j = 0; j < 4; j++) bi[j] = lin_b[n0 + tx * 4 + j];
#pragma unroll
    for (int i = 0; i < 8; i++) {
        size_t base = (size_t)(b0 + ty * 8 + i) * HH + n0 + tx * 4;
#pragma unroll
        for (int j = 0; j < 4; j++) g_eqc[base + j] = acc[i][j] + bi[j];
    }
}

// ===========================================================================
// logits[m] = X_m @ er^T, writes d_out
// ===========================================================================
__global__ __launch_bounds__(128) void logits_kernel(float* __restrict__ out, int p) {
    const int m = blockIdx.z;
    const float* __restrict__ X  = (m == 0) ? g_h[p]
                                 : (m == 1) ? g_h[p] + (size_t)BB * HH
                                            : g_eqc;
    const float* __restrict__ er = g_h[p] + (size_t)2 * BB * HH;
    const int n0 = blockIdx.x * 64;
    const int b0 = blockIdx.y * 64;

    __shared__ float As[16][65];
    __shared__ float Bs[16][65];

    const int tid = threadIdx.x;
    const int tx = tid & 15, ty = tid >> 4;

    float acc[8][4];
#pragma unroll
    for (int i = 0; i < 8; i++)
#pragma unroll
        for (int j = 0; j < 4; j++) acc[i][j] = 0.0f;

    for (int k0 = 0; k0 < HH; k0 += 16) {
#pragma unroll
        for (int l = 0; l < 8; l++) {
            int idx = tid + l * 128;
            int k = idx & 15, i = idx >> 4;
            As[k][i] = X[(size_t)(b0 + i) * HH + (k0 + k)];
            Bs[k][i] = er[(size_t)(n0 + i) * HH + (k0 + k)];
        }
        __syncthreads();
#pragma unroll
        for (int k = 0; k < 16; k++) {
            float a[8], b[4];
#pragma unroll
            for (int i = 0; i < 8; i++) a[i] = As[k][ty * 8 + i];
#pragma unroll
            for (int j = 0; j < 4; j++) b[j] = Bs[k][tx * 4 + j];
#pragma unroll
            for (int i = 0; i < 8; i++)
#pragma unroll
                for (int j = 0; j < 4; j++) acc[i][j] += a[i] * b[j];
        }
        __syncthreads();
    }

#pragma unroll
    for (int i = 0; i < 8; i++) {
        size_t base = (size_t)m * BB * BB + (size_t)(b0 + ty * 8 + i) * BB + n0 + tx * 4;
#pragma unroll
        for (int j = 0; j < 4; j++) out[base + j] = acc[i][j];
    }
}

// ===========================================================================
// Row softmax over 3*B rows of length B, in-place on d_out.
// ===========================================================================
__global__ __launch_bounds__(256) void softmax_kernel(float* __restrict__ out) {
    float* prow = out + (size_t)blockIdx.x * BB;
    __shared__ float red[256];
    const int tid = threadIdx.x;

    float v[4];
    float mx = -1e30f;
#pragma unroll
    for (int l = 0; l < 4; l++) {
        v[l] = prow[tid + l * 256];
        mx = fmaxf(mx, v[l]);
    }
    red[tid] = mx;
    __syncthreads();
    for (int s = 128; s > 0; s >>= 1) {
        if (tid < s) red[tid] = fmaxf(red[tid], red[tid + s]);
        __syncthreads();
    }
    mx = red[0];
    __syncthreads();

    float sum = 0.0f;
#pragma unroll
    for (int l = 0; l < 4; l++) {
        v[l] = __expf(v[l] - mx);
        sum += v[l];
    }
    red[tid] = sum;
    __syncthreads();
    for (int s = 128; s > 0; s >>= 1) {
        if (tid < s) red[tid] += red[tid + s];
        __syncthreads();
    }
    float inv = 1.0f / red[0];
#pragma unroll
    for (int l = 0; l < 4; l++) prow[tid + l * 256] = v[l] * inv;
}

// ===========================================================================
// Launch
// ===========================================================================
extern "C" void kernel_launch(void* const* d_in, const int* in_sizes, int n_in,
                              void* d_out, int out_size) {
    (void)in_sizes; (void)n_in; (void)out_size;

    EncPack P;
    const int* toks[3] = { (const int*)d_in[0], (const int*)d_in[1], (const int*)d_in[2] };
    for (int e = 0; e < 3; e++) {
        int b = 3 + e * 5;
        P.e[e].tok = toks[e];
        P.e[e].emb = (const float*)d_in[b + 0];
        P.e[e].wih = (const float*)d_in[b + 1];
        P.e[e].whh = (const float*)d_in[b + 2];
        P.e[e].bih = (const float*)d_in[b + 3];
        P.e[e].bhh = (const float*)d_in[b + 4];
    }
    const float* lin_w = (const float*)d_in[18];
    const float* lin_b = (const float*)d_in[19];
    float* out = (float*)d_out;

    const int SMEM_DYN = (6 * STGW) * 4 + 128 * 4;   // 98816 B
    cudaFuncSetAttribute(step_tc_kernel,
                         cudaFuncAttributeMaxDynamicSharedMemorySize, SMEM_DYN);

    zero_h_kernel<<<(3 * BB * HH + 255) / 256, 256>>>();
    {
        size_t n = (size_t)3 * 16 * 128 * 640;
        pack_w_kernel<<<(unsigned)((n + 255) / 256), 256>>>(P);
    }
    {
        size_t n = (size_t)3 * VV * 128;
        pack_emb_kernel<<<(unsigned)((n + 255) / 256), 256>>>(P);
    }

    int p = 0;
    for (int t = SS - 1; t >= 0; --t) {
        step_tc_kernel<<<dim3(16, BB / 128, 3), 256, SMEM_DYN>>>(P, t, p);
        p ^= 1;
    }

    eqc_kernel<<<dim3(HH / 64, BB / 64), 128>>>(lin_w, lin_b, p);
    logits_kernel<<<dim3(BB / 64, BB / 64, 3), 128>>>(out, p);
    softmax_kernel<<<3 * BB, 256>>>(out);
}

// round 17
// speedup vs baseline: 2.6453x; 1.2815x over previous
#include <cuda_runtime.h>
#include <cuda_fp16.h>
#include <cstdint>
#include <math.h>

#define BB 1024
#define SS 64
#define EE 100
#define HH 512
#define VV 50000

// ---------------------------------------------------------------------------
// Static device scratch (no allocations allowed)
// g_h:   fp32 hidden, NATURAL order (blend path + tail kernels)
// g_hhf: fp16 hidden, K-PERMUTED within 16-groups (GEMM A path)
// ---------------------------------------------------------------------------
__device__ float    g_h[2][3 * BB * HH];
__device__ __half   g_hhf[2][3 * BB * HH];
__device__ float    g_eqc[BB * HH];
__device__ __half   g_wpk[(size_t)3 * 16 * 128 * 640];  // packed W, 7.9 MB
__device__ __half   g_embp[(size_t)3 * VV * 128];       // packed emb, 38.4 MB

struct Enc {
    const int*   tok;
    const float* emb;
    const float* wih;
    const float* whh;
    const float* bih;
    const float* bhh;
};
struct EncPack { Enc e[3]; };

__device__ __forceinline__ float sigmoidf_(float x) {
    return 1.0f / (1.0f + __expf(-x));
}

// ===========================================================================
// PTX helpers (sm_80-portable)
// ===========================================================================
__device__ __forceinline__ void cp16(uint32_t dst, const void* src) {
    asm volatile("cp.async.cg.shared.global [%0], [%1], 16;" :: "r"(dst), "l"(src));
}
#define CP_COMMIT() asm volatile("cp.async.commit_group;" ::: "memory")
#define CP_WAITG1() asm volatile("cp.async.wait_group 1;" ::: "memory")

__device__ __forceinline__ uint32_t smem_u32(const void* p) {
    uint32_t a;
    asm("{ .reg .u64 t; cvta.to.shared.u64 t, %1; cvt.u32.u64 %0, t; }" : "=r"(a) : "l"(p));
    return a;
}
__device__ __forceinline__ void mma16(float* d, const uint32_t* a, uint32_t b0, uint32_t b1) {
    asm volatile("mma.sync.aligned.m16n8k16.row.col.f32.f16.f16.f32 "
                 "{%0,%1,%2,%3}, {%4,%5,%6,%7}, {%8,%9}, {%0,%1,%2,%3};"
                 : "+f"(d[0]), "+f"(d[1]), "+f"(d[2]), "+f"(d[3])
                 : "r"(a[0]), "r"(a[1]), "r"(a[2]), "r"(a[3]), "r"(b0), "r"(b1));
}

// K-permutation within 16-groups for m16n8k16 frags:
// source k -> position 4*((k>>1)&3) + (k&1) + 2*((k>>3)&1)
// => thread tg's halves {2tg, 2tg+1, 2tg+8, 2tg+9} land at positions 4tg..4tg+3.
__device__ __forceinline__ int p16(int k) {
    return (((k >> 1) & 3) << 2) | (k & 1) | (((k >> 3) & 1) << 1);
}

// ===========================================================================
// Chunk compute: sections {0, 1, ALT} over NG k16-groups.
// ALL indices compile-time -> acc/a arrays stay in registers.
// ===========================================================================
template<int ALT, int NG>
__device__ __forceinline__ void compute_chunk(
    float (&acc)[2][2][4][4],
    const uint32_t* __restrict__ Ast, const uint32_t* __restrict__ Bst,
    int warp_m, int warp_n, int gr, int tg, int xg)
{
#pragma unroll
    for (int g = 0; g < NG; g++) {
        const int w  = 8 * g + 2 * tg;
        const int uw = (((w >> 2) ^ (xg << 1)) << 2) | (w & 3);
        uint32_t a[2][4];
#pragma unroll
        for (int mt = 0; mt < 2; mt++) {
            int rb = warp_m * 32 + mt * 16 + gr;
            uint2 lo = *(const uint2*)&Ast[rb * 32 + uw];
            uint2 hi = *(const uint2*)&Ast[(rb + 8) * 32 + uw];
            a[mt][0] = lo.x; a[mt][2] = lo.y; a[mt][1] = hi.x; a[mt][3] = hi.y;
        }
#pragma unroll
        for (int jg_l = 0; jg_l < 2; jg_l++) {
            {
                int n = warp_n * 64 + (jg_l * 4 + 0) * 8 + gr;
                uint2 bb = *(const uint2*)&Bst[n * 32 + uw];
                mma16(acc[0][jg_l][0], a[0], bb.x, bb.y);
                mma16(acc[1][jg_l][0], a[1], bb.x, bb.y);
            }
            {
                int n = warp_n * 64 + (jg_l * 4 + 1) * 8 + gr;
                uint2 bb = *(const uint2*)&Bst[n * 32 + uw];
                mma16(acc[0][jg_l][1], a[0], bb.x, bb.y);
                mma16(acc[1][jg_l][1], a[1], bb.x, bb.y);
            }
            {
                int n = warp_n * 64 + (jg_l * 4 + ALT) * 8 + gr;
                uint2 bb = *(const uint2*)&Bst[n * 32 + uw];
                mma16(acc[0][jg_l][ALT], a[0], bb.x, bb.y);
                mma16(acc[1][jg_l][ALT], a[1], bb.x, bb.y);
            }
        }
    }
}

// ===========================================================================
// Init + pack kernels
// ===========================================================================
__global__ void zero_h_kernel() {
    size_t i = (size_t)blockIdx.x * blockDim.x + threadIdx.x;
    if (i < (size_t)3 * BB * HH) {
        g_h[0][i]   = 0.0f;
        g_hhf[0][i] = __float2half_rn(0.0f);
    }
}

// W panels: [e][jt(16)][n(128)][k(640), p16-permuted].
__global__ void pack_w_kernel(EncPack P) {
    size_t id = (size_t)blockIdx.x * blockDim.x + threadIdx.x;
    if (id >= (size_t)3 * 16 * 128 * 640) return;
    int k  = (int)(id % 640);
    int n  = (int)((id / 640) % 128);
    int jt = (int)((id / (640 * 128)) % 16);
    int e  = (int)(id / (640 * 128 * 16));
    int nt = n >> 3, jg = nt >> 2, sec = nt & 3, jj = n & 7;
    int j = jt * 32 + jg * 8 + jj;
    float v = 0.0f;
    if (k < 512) {
        if (sec < 3) v = P.e[e].whh[(size_t)(sec * HH + j) * HH + k];
    } else {
        int kx = k - 512;
        if (kx < EE) {
            if (sec < 2)       v = P.e[e].wih[(size_t)(sec * HH + j) * EE + kx];
            else if (sec == 3) v = P.e[e].wih[(size_t)(2 * HH + j) * EE + kx];
        }
    }
    size_t dst = (((size_t)(e * 16 + jt) * 128 + n) * 640) + (k & ~15) + p16(k & 15);
    g_wpk[dst] = __float2half_rn(v);
}

// emb: [e][v][k(128), p16-permuted, zero-padded past E=100]
__global__ void pack_emb_kernel(EncPack P) {
    size_t id = (size_t)blockIdx.x * blockDim.x + threadIdx.x;
    if (id >= (size_t)3 * VV * 128) return;
    int k = (int)(id & 127);
    int v = (int)((id >> 7) % VV);
    int e = (int)(id / ((size_t)VV * 128));
    float x = (k < EE) ? P.e[e].emb[(size_t)v * EE + k] : 0.0f;
    g_embp[((size_t)e * VV + v) * 128 + (k & ~15) + p16(k & 15)] = __float2half_rn(x);
}

// ===========================================================================
// Fused GRU step for ONE encoder (e is a parameter; 3 encoder chains run on
// forked streams so their step tails overlap).  fp16 m16n8k16, fp32 accum.
// M=128 x N=128 x K=640, zero-section skip (compile-time), 3-stage cp.async
// pipeline, XOR-swizzled smem, one __syncthreads per chunk.
// grid (16, 8), block 256 (warps 4m x 2n), 2 CTAs/SM, 98.8 KB dyn smem.
// ===========================================================================
#define NCHK 10
#define STGW (128 * 32)          // uint32 words per stage per operand

__global__ __launch_bounds__(256, 2) void step_tc_kernel(EncPack P, int t, int p, int e) {
    extern __shared__ uint32_t dsm[];
    uint32_t* As = dsm;                       // [3][STGW]
    uint32_t* Bs = dsm + 3 * STGW;            // [3][STGW]
    int*      stok = (int*)(dsm + 6 * STGW);  // [128]

    const Enc ep = P.e[e];
    const int jt = blockIdx.x;
    const int j0 = jt * 32;
    const int b0 = blockIdx.y * 128;

    const float* __restrict__ hin  = g_h[p]     + (size_t)e * BB * HH;
    float*       __restrict__ hout = g_h[p ^ 1] + (size_t)e * BB * HH;
    const __half* __restrict__ hhf  = g_hhf[p]     + (size_t)e * BB * HH;
    __half*       __restrict__ hhfo = g_hhf[p ^ 1] + (size_t)e * BB * HH;
    const __half* __restrict__ Wp   = g_wpk  + ((size_t)(e * 16 + jt) * 128) * 640;
    const __half* __restrict__ embp = g_embp + (size_t)e * VV * 128;

    const int tid = threadIdx.x;
    const int lane = tid & 31, wid = tid >> 5;
    const int gr = lane >> 2, tg = lane & 3;
    const int warp_m = wid & 3, warp_n = wid >> 2;
    const int xg = gr & 3;

    const uint32_t sA = smem_u32(As), sB = smem_u32(Bs);

    if (tid < 128) stok[tid] = ep.tok[(b0 + tid) * SS + t];
    __syncthreads();

    float acc[2][2][4][4];           // [mt][jg_l][sec][dreg]
#pragma unroll
    for (int a = 0; a < 2; a++)
#pragma unroll
        for (int b = 0; b < 2; b++)
#pragma unroll
            for (int s = 0; s < 4; s++)
#pragma unroll
                for (int c = 0; c < 4; c++) acc[a][b][s][c] = 0.0f;

    auto load_chunk = [&](int c, int st) {
        const uint32_t aB = sA + (uint32_t)st * STGW * 4;
        const uint32_t bB = sB + (uint32_t)st * STGW * 4;
        const int skip_sec = (c < 8) ? 3 : 2;    // dead B section this chunk
#pragma unroll
        for (int it = 0; it < 4; it++) {
            int idx = tid + it * 256;            // [0,1024): row 0..127, kq 0..7
            int row = idx >> 3, kq = idx & 7;
            int q = kq ^ ((row & 3) << 1);       // swizzled uint4 slot
            uint32_t dof = (uint32_t)(row * 32 + q * 4) * 4;
            const void* asrc = (c < 8)
                ? (const void*)(hhf + (size_t)(b0 + row) * HH + c * 64 + kq * 8)
                : (const void*)(embp + (size_t)stok[row] * 128 + (c - 8) * 64 + kq * 8);
            cp16(aB + dof, asrc);
            if (((row >> 3) & 3) != skip_sec)
                cp16(bB + dof, Wp + (size_t)row * 640 + c * 64 + kq * 8);
        }
    };

    load_chunk(0, 0); CP_COMMIT();
    load_chunk(1, 1); CP_COMMIT();

    int s_cur = 0;                    // stage of chunk c
    int s_ld  = 2;                    // stage of chunk c+2
    for (int c = 0; c < NCHK; c++) {
        CP_WAITG1();
        __syncthreads();
        if (c + 2 < NCHK) {
            load_chunk(c + 2, s_ld);
            CP_COMMIT();
        }
        const uint32_t* Ast = As + s_cur * STGW;
        const uint32_t* Bst = Bs + s_cur * STGW;
        if (c < 8)
            compute_chunk<2, 4>(acc, Ast, Bst, warp_m, warp_n, gr, tg, xg);
        else if (c == 8)
            compute_chunk<3, 4>(acc, Ast, Bst, warp_m, warp_n, gr, tg, xg);
        else
            compute_chunk<3, 3>(acc, Ast, Bst, warp_m, warp_n, gr, tg, xg);
        s_cur = (s_cur == 2) ? 0 : s_cur + 1;
        s_ld  = (s_ld  == 2) ? 0 : s_ld  + 1;
    }

    // ---- GRU epilogue (per-thread, in-register) ----
    float br[2][2], bz[2][2], bnh[2][2], bni[2][2];
    int   jp[2][2];
#pragma unroll
    for (int jg_l = 0; jg_l < 2; jg_l++)
#pragma unroll
        for (int cc = 0; cc < 2; cc++) {
            int j = j0 + (warp_n * 2 + jg_l) * 8 + tg * 2 + cc;
            br[jg_l][cc]  = ep.bih[j]          + ep.bhh[j];
            bz[jg_l][cc]  = ep.bih[HH + j]     + ep.bhh[HH + j];
            bnh[jg_l][cc] = ep.bhh[2 * HH + j];
            bni[jg_l][cc] = ep.bih[2 * HH + j];
            jp[jg_l][cc]  = (j & ~15) | p16(j & 15);   // fp16 permuted pos
        }

#pragma unroll
    for (int mt = 0; mt < 2; mt++) {
#pragma unroll
        for (int rp = 0; rp < 2; rp++) {
            const int row = b0 + warp_m * 32 + mt * 16 + gr + rp * 8;
            const float* hrow = hin + (size_t)row * HH;
            float*       orow = hout + (size_t)row * HH;
            __half*      ohrow = hhfo + (size_t)row * HH;
#pragma unroll
            for (int jg_l = 0; jg_l < 2; jg_l++) {
#pragma unroll
                for (int cc = 0; cc < 2; cc++) {
                    const int j = j0 + (warp_n * 2 + jg_l) * 8 + tg * 2 + cc;
                    const int k = rp * 2 + cc;
                    float r = sigmoidf_(acc[mt][jg_l][0][k] + br[jg_l][cc]);
                    float z = sigmoidf_(acc[mt][jg_l][1][k] + bz[jg_l][cc]);
                    float n = tanhf(acc[mt][jg_l][3][k] + bni[jg_l][cc] +
                                    r * (acc[mt][jg_l][2][k] + bnh[jg_l][cc]));
                    float hv = (1.0f - z) * n + z * hrow[j];
                    orow[j] = hv;                              // fp32 master
                    ohrow[jp[jg_l][cc]] = __float2half_rn(hv); // fp16 GEMM copy
                }
            }
        }
    }
}

// ===========================================================================
// eqc = ((eq + ec) * 0.5) @ lin_w^T + lin_b   (natural-order fp32 h)
// ===========================================================================
__global__ __launch_bounds__(128) void eqc_kernel(const float* __restrict__ lin_w,
                                                  const float* __restrict__ lin_b,
                                                  int p) {
    const float* __restrict__ hq = g_h[p];
    const float* __restrict__ hc = g_h[p] + (size_t)BB * HH;
    const int n0 = blockIdx.x * 64;
    const int b0 = blockIdx.y * 64;

    __shared__ float As[16][65];
    __shared__ float Bs[16][65];

    const int tid = threadIdx.x;
    const int tx = tid & 15, ty = tid >> 4;

    float acc[8][4];
#pragma unroll
    for (int i = 0; i < 8; i++)
#pragma unroll
        for (int j = 0; j < 4; j++) acc[i][j] = 0.0f;

    for (int k0 = 0; k0 < HH; k0 += 16) {
#pragma unroll
        for (int l = 0; l < 8; l++) {
            int idx = tid + l * 128;
            int k = idx & 15, i = idx >> 4;
            size_t ga = (size_t)(b0 + i) * HH + (k0 + k);
            As[k][i] = 0.5f * (hq[ga] + hc[ga]);
            Bs[k][i] = lin_w[(size_t)(n0 + i) * HH + (k0 + k)];
        }
        __syncthreads();
#pragma unroll
        for (int k = 0; k < 16; k++) {
            float a[8], b[4];
#pragma unroll
            for (int i = 0; i < 8; i++) a[i] = As[k][ty * 8 + i];
#pragma unroll
            for (int j = 0; j < 4; j++) b[j] = Bs[k][tx * 4 + j];
#pragma unroll
            for (int i = 0; i < 8; i++)
#pragma unroll
                for (int j = 0; j < 4; j++) acc[i][j] += a[i] * b[j];
        }
        __syncthreads();
    }

    float bi[4];
#pragma unroll
    for (int j = 0; j < 4; j++) bi[j] = lin_b[n0 + tx * 4 + j];
#pragma unroll
    for (int i = 0; i < 8; i++) {
        size_t base = (size_t)(b0 + ty * 8 + i) * HH + n0 + tx * 4;
#pragma unroll
        for (int j = 0; j < 4; j++) g_eqc[base + j] = acc[i][j] + bi[j];
    }
}

// ===========================================================================
// logits[m] = X_m @ er^T, writes d_out
// ===========================================================================
__global__ __launch_bounds__(128) void logits_kernel(float* __restrict__ out, int p) {
    const int m = blockIdx.z;
    const float* __restrict__ X  = (m == 0) ? g_h[p]
                                 : (m == 1) ? g_h[p] + (size_t)BB * HH
                                            : g_eqc;
    const float* __restrict__ er = g_h[p] + (size_t)2 * BB * HH;
    const int n0 = blockIdx.x * 64;
    const int b0 = blockIdx.y * 64;

    __shared__ float As[16][65];
    __shared__ float Bs[16][65];

    const int tid = threadIdx.x;
    const int tx = tid & 15, ty = tid >> 4;

    float acc[8][4];
#pragma unroll
    for (int i = 0; i < 8; i++)
#pragma unroll
        for (int j = 0; j < 4; j++) acc[i][j] = 0.0f;

    for (int k0 = 0; k0 < HH; k0 += 16) {
#pragma unroll
        for (int l = 0; l < 8; l++) {
            int idx = tid + l * 128;
            int k = idx & 15, i = idx >> 4;
            As[k][i] = X[(size_t)(b0 + i) * HH + (k0 + k)];
            Bs[k][i] = er[(size_t)(n0 + i) * HH + (k0 + k)];
        }
        __syncthreads();
#pragma unroll
        for (int k = 0; k < 16; k++) {
            float a[8], b[4];
#pragma unroll
            for (int i = 0; i < 8; i++) a[i] = As[k][ty * 8 + i];
#pragma unroll
            for (int j = 0; j < 4; j++) b[j] = Bs[k][tx * 4 + j];
#pragma unroll
            for (int i = 0; i < 8; i++)
#pragma unroll
                for (int j = 0; j < 4; j++) acc[i][j] += a[i] * b[j];
        }
        __syncthreads();
    }

#pragma unroll
    for (int i = 0; i < 8; i++) {
        size_t base = (size_t)m * BB * BB + (size_t)(b0 + ty * 8 + i) * BB + n0 + tx * 4;
#pragma unroll
        for (int j = 0; j < 4; j++) out[base + j] = acc[i][j];
    }
}

// ===========================================================================
// Row softmax over 3*B rows of length B, in-place on d_out.
// ===========================================================================
__global__ __launch_bounds__(256) void softmax_kernel(float* __restrict__ out) {
    float* prow = out + (size_t)blockIdx.x * BB;
    __shared__ float red[256];
    const int tid = threadIdx.x;

    float v[4];
    float mx = -1e30f;
#pragma unroll
    for (int l = 0; l < 4; l++) {
        v[l] = prow[tid + l * 256];
        mx = fmaxf(mx, v[l]);
    }
    red[tid] = mx;
    __syncthreads();
    for (int s = 128; s > 0; s >>= 1) {
        if (tid < s) red[tid] = fmaxf(red[tid], red[tid + s]);
        __syncthreads();
    }
    mx = red[0];
    __syncthreads();

    float sum = 0.0f;
#pragma unroll
    for (int l = 0; l < 4; l++) {
        v[l] = __expf(v[l] - mx);
        sum += v[l];
    }
    red[tid] = sum;
    __syncthreads();
    for (int s = 128; s > 0; s >>= 1) {
        if (tid < s) red[tid] += red[tid + s];
        __syncthreads();
    }
    float inv = 1.0f / red[0];
#pragma unroll
    for (int l = 0; l < 4; l++) prow[tid + l * 256] = v[l] * inv;
}

// ===========================================================================
// Launch.  Three encoder chains fork onto side streams (event fork/join —
// stream-capture-safe); their step tails overlap, eliminating the ~35%
// wave-quantization waste of the fused 384-CTA steps.
// ===========================================================================
extern "C" void kernel_launch(void* const* d_in, const int* in_sizes, int n_in,
                              void* d_out, int out_size) {
    (void)in_sizes; (void)n_in; (void)out_size;

    EncPack P;
    const int* toks[3] = { (const int*)d_in[0], (const int*)d_in[1], (const int*)d_in[2] };
    for (int e = 0; e < 3; e++) {
        int b = 3 + e * 5;
        P.e[e].tok = toks[e];
        P.e[e].emb = (const float*)d_in[b + 0];
        P.e[e].wih = (const float*)d_in[b + 1];
        P.e[e].whh = (const float*)d_in[b + 2];
        P.e[e].bih = (const float*)d_in[b + 3];
        P.e[e].bhh = (const float*)d_in[b + 4];
    }
    const float* lin_w = (const float*)d_in[18];
    const float* lin_b = (const float*)d_in[19];
    float* out = (float*)d_out;

    // One-time stream/event setup (host-side resources only; no device allocs).
    static cudaStream_t s1 = nullptr, s2 = nullptr;
    static cudaEvent_t  evFork = nullptr, evJ1 = nullptr, evJ2 = nullptr;
    if (s1 == nullptr) {
        cudaStreamCreateWithFlags(&s1, cudaStreamNonBlocking);
        cudaStreamCreateWithFlags(&s2, cudaStreamNonBlocking);
        cudaEventCreateWithFlags(&evFork, cudaEventDisableTiming);
        cudaEventCreateWithFlags(&evJ1,   cudaEventDisableTiming);
        cudaEventCreateWithFlags(&evJ2,   cudaEventDisableTiming);
    }

    const int SMEM_DYN = (6 * STGW) * 4 + 128 * 4;   // 98816 B
    cudaFuncSetAttribute(step_tc_kernel,
                         cudaFuncAttributeMaxDynamicSharedMemorySize, SMEM_DYN);

    zero_h_kernel<<<(3 * BB * HH + 255) / 256, 256>>>();
    {
        size_t n = (size_t)3 * 16 * 128 * 640;
        pack_w_kernel<<<(unsigned)((n + 255) / 256), 256>>>(P);
    }
    {
        size_t n = (size_t)3 * VV * 128;
        pack_emb_kernel<<<(unsigned)((n + 255) / 256), 256>>>(P);
    }

    // Fork: side streams wait for init/packs on the main stream.
    cudaEventRecord(evFork, 0);
    cudaStreamWaitEvent(s1, evFork, 0);
    cudaStreamWaitEvent(s2, evFork, 0);

    // Three independent recurrence chains: e=0 on main, e=1 on s1, e=2 on s2.
    int p = 0;
    for (int t = SS - 1; t >= 0; --t) {
        step_tc_kernel<<<dim3(16, BB / 128), 256, SMEM_DYN, 0 >>>(P, t, p, 0);
        step_tc_kernel<<<dim3(16, BB / 128), 256, SMEM_DYN, s1>>>(P, t, p, 1);
        step_tc_kernel<<<dim3(16, BB / 128), 256, SMEM_DYN, s2>>>(P, t, p, 2);
        p ^= 1;
    }

    // Join: main stream waits for both side chains.
    cudaEventRecord(evJ1, s1);
    cudaEventRecord(evJ2, s2);
    cudaStreamWaitEvent(0, evJ1, 0);
    cudaStreamWaitEvent(0, evJ2, 0);

    eqc_kernel<<<dim3(HH / 64, BB / 64), 128>>>(lin_w, lin_b, p);
    logits_kernel<<<dim3(BB / 64, BB / 64, 3), 128>>>(out, p);
    softmax_kernel<<<3 * BB, 256>>>(out);
}